// round 9
// baseline (speedup 1.0000x reference)
#include <cuda_runtime.h>
#include <math.h>

// GATLayer: h[100000,128] f32, W[64,128] f32, src[E] i32, dst[E] i32 -> out[100000,64] f32
// (harness canonicalizes the reference's int64 index arrays to int32 — the stub
//  documents only float32/int32/bfloat16 conversions)
//
// Pipeline (no fp32 atomics anywhere):
//   K0 init:     deg = 0
//   K1 gemm:     z = h @ W^T                        (register-tiled SGEMM)
//   K2 score:    e = leaky_relu(z[src].z[dst]); deg[dst]++   (int atomics)
//   K3a/b/c:     exclusive scan deg -> off          (3-kernel scan)
//   K4 scatter:  pack {src, e} into CSR order by dst (int atomics for cursor)
//   K5 agg:      per-node softmax + weighted sum of z[src] + ELU -> out
//                (register-batched fast path for degree <= 32; __expf/MUFU)

#define NODES_CAP 100000
#define EDGES_CAP 1600000
#define IN_DIM 128
#define OUT_DIM 64
#define SCAN_BLK 256
#define MAX_BLKS 512   // ceil(100000/256)=391 <= 512

__device__ float g_z[(size_t)NODES_CAP * OUT_DIM];   // 25.6 MB (L2-resident)
__device__ float g_e[EDGES_CAP];                     // edge scores (edge order)
__device__ int2  g_pack[EDGES_CAP];                  // CSR-ordered {src, e_bits}
__device__ int   g_deg[NODES_CAP];                   // counts, then scatter cursor
__device__ int   g_off[NODES_CAP + 1];               // CSR offsets
__device__ int   g_bsum[MAX_BLKS];                   // scan partials

// ---------------------------------------------------------------------------
__global__ void init_kernel(int n_nodes) {
    int i = blockIdx.x * blockDim.x + threadIdx.x;
    if (i < n_nodes) g_deg[i] = 0;
}

// ---------------------------------------------------------------------------
// SGEMM: z[n][o] = sum_k h[n][k] * W[o][k]
// Block tile 128x64, 256 threads, 4x8 micro-tile. W fully staged in SMEM.
__global__ __launch_bounds__(256) void gemm_kernel(
    const float* __restrict__ h, const float* __restrict__ W, int n_nodes)
{
    __shared__ float ws[IN_DIM][OUT_DIM];   // [k][o]
    __shared__ float hs[16][132];           // [k][node], padded

    int tid = threadIdx.x;

    for (int i = tid; i < OUT_DIM * IN_DIM / 4; i += 256) {
        int o  = i >> 5;
        int k4 = (i & 31) << 2;
        float4 w4 = ((const float4*)W)[i];
        ws[k4 + 0][o] = w4.x;
        ws[k4 + 1][o] = w4.y;
        ws[k4 + 2][o] = w4.z;
        ws[k4 + 3][o] = w4.w;
    }

    int nr = tid >> 3;
    int oc = tid & 7;
    int node_base = blockIdx.x * 128;

    float acc[4][8];
#pragma unroll
    for (int i = 0; i < 4; i++)
#pragma unroll
        for (int j = 0; j < 8; j++) acc[i][j] = 0.f;

    for (int kc = 0; kc < IN_DIM; kc += 16) {
        __syncthreads();
#pragma unroll
        for (int i = tid; i < 512; i += 256) {
            int n = i >> 2;
            int q = i & 3;
            int gn = node_base + n;
            float4 v = make_float4(0.f, 0.f, 0.f, 0.f);
            if (gn < n_nodes)
                v = *(const float4*)(h + (size_t)gn * IN_DIM + kc + (q << 2));
            hs[(q << 2) + 0][n] = v.x;
            hs[(q << 2) + 1][n] = v.y;
            hs[(q << 2) + 2][n] = v.z;
            hs[(q << 2) + 3][n] = v.w;
        }
        __syncthreads();
#pragma unroll
        for (int k = 0; k < 16; k++) {
            float4 a  = *(const float4*)&hs[k][nr << 2];
            float4 b0 = *(const float4*)&ws[kc + k][oc << 3];
            float4 b1 = *(const float4*)&ws[kc + k][(oc << 3) + 4];
            float av[4] = {a.x, a.y, a.z, a.w};
            float bv[8] = {b0.x, b0.y, b0.z, b0.w, b1.x, b1.y, b1.z, b1.w};
#pragma unroll
            for (int i = 0; i < 4; i++)
#pragma unroll
                for (int j = 0; j < 8; j++)
                    acc[i][j] += av[i] * bv[j];
        }
    }

#pragma unroll
    for (int i = 0; i < 4; i++) {
        int gn = node_base + (nr << 2) + i;
        if (gn < n_nodes) {
            float4 r0 = make_float4(acc[i][0], acc[i][1], acc[i][2], acc[i][3]);
            float4 r1 = make_float4(acc[i][4], acc[i][5], acc[i][6], acc[i][7]);
            *(float4*)(g_z + (size_t)gn * OUT_DIM + (oc << 3))     = r0;
            *(float4*)(g_z + (size_t)gn * OUT_DIM + (oc << 3) + 4) = r1;
        }
    }
}

// ---------------------------------------------------------------------------
// e[edge] = leaky_relu(dot(z[src], z[dst])); deg[dst]++
// 16 lanes per edge; float4 loads (256B per row, half-warp-coalesced).
__global__ __launch_bounds__(256) void edge_score_kernel(
    const int* __restrict__ src, const int* __restrict__ dst, int n_edges)
{
    long long t = (long long)blockIdx.x * blockDim.x + threadIdx.x;
    int edge = (int)(t >> 4);
    int lane = threadIdx.x & 15;
    if (edge >= n_edges) return;

    int s = src[edge];
    int d = dst[edge];

    float4 a = *(const float4*)(g_z + (size_t)s * OUT_DIM + (lane << 2));
    float4 b = *(const float4*)(g_z + (size_t)d * OUT_DIM + (lane << 2));
    float dot = a.x * b.x + a.y * b.y + a.z * b.z + a.w * b.w;
    dot += __shfl_xor_sync(0xffffffffu, dot, 8);
    dot += __shfl_xor_sync(0xffffffffu, dot, 4);
    dot += __shfl_xor_sync(0xffffffffu, dot, 2);
    dot += __shfl_xor_sync(0xffffffffu, dot, 1);

    if (lane == 0) {
        g_e[edge] = dot > 0.f ? dot : 0.2f * dot;
        atomicAdd(&g_deg[d], 1);
    }
}

// ---------------------------------------------------------------------------
// Exclusive scan of g_deg into g_off (3 kernels).
__global__ __launch_bounds__(SCAN_BLK) void scan_part_kernel(int n) {
    __shared__ int sm[SCAN_BLK];
    int tid = threadIdx.x;
    int i = blockIdx.x * SCAN_BLK + tid;
    int v = (i < n) ? g_deg[i] : 0;
    sm[tid] = v;
    __syncthreads();
#pragma unroll
    for (int o = 1; o < SCAN_BLK; o <<= 1) {
        int t = (tid >= o) ? sm[tid - o] : 0;
        __syncthreads();
        sm[tid] += t;
        __syncthreads();
    }
    if (i < n) g_off[i] = sm[tid] - v;          // exclusive within block
    if (tid == SCAN_BLK - 1) g_bsum[blockIdx.x] = sm[tid];
}

__global__ __launch_bounds__(MAX_BLKS) void scan_top_kernel(int nblocks) {
    __shared__ int sm[MAX_BLKS];
    int tid = threadIdx.x;
    int v = (tid < nblocks) ? g_bsum[tid] : 0;
    sm[tid] = v;
    __syncthreads();
#pragma unroll
    for (int o = 1; o < MAX_BLKS; o <<= 1) {
        int t = (tid >= o) ? sm[tid - o] : 0;
        __syncthreads();
        sm[tid] += t;
        __syncthreads();
    }
    if (tid < nblocks) g_bsum[tid] = sm[tid] - v;  // exclusive
}

__global__ __launch_bounds__(SCAN_BLK) void scan_add_kernel(int n, int n_edges) {
    int i = blockIdx.x * SCAN_BLK + threadIdx.x;
    if (i < n) {
        g_off[i] += g_bsum[blockIdx.x];
        g_deg[i] = 0;                           // reset -> scatter cursor
    }
    if (i == 0) g_off[n] = n_edges;
}

// ---------------------------------------------------------------------------
// Scatter packed {src, e} into CSR order by dst. All reads coalesced;
// one random 8B write per edge.
__global__ __launch_bounds__(256) void scatter_kernel(
    const int* __restrict__ src, const int* __restrict__ dst, int n_edges)
{
    int i = blockIdx.x * blockDim.x + threadIdx.x;
    if (i >= n_edges) return;
    int d = dst[i];
    int pos = atomicAdd(&g_deg[d], 1);
    int2 p;
    p.x = src[i];
    p.y = __float_as_int(g_e[i]);
    g_pack[g_off[d] + pos] = p;
}

// ---------------------------------------------------------------------------
// One warp per node: softmax over incoming edges + weighted sum of z[src] + ELU.
// Metadata comes as contiguous packed {src, e} — no indirection, no gathers
// except the z rows themselves. __expf = MUFU.EX2 fast path (~1e-7 rel err).
__global__ __launch_bounds__(256) void agg_kernel(
    float* __restrict__ out, int n_nodes)
{
    int warp = (blockIdx.x * blockDim.x + threadIdx.x) >> 5;
    int lane = threadIdx.x & 31;
    if (warp >= n_nodes) return;

    int off = g_off[warp];
    int end = g_off[warp + 1];
    int cnt = end - off;

    float ax = 0.f, ay = 0.f;
    const float2* zp = (const float2*)g_z;

    if (cnt <= 32) {
        // ---- fast path: one contiguous parallel metadata load ----
        bool valid = lane < cnt;
        int2 p = valid ? g_pack[off + lane] : make_int2(0, 0xff800000); // e=-inf
        int   sn = p.x;
        float ev = __int_as_float(p.y);

        float m = ev;
#pragma unroll
        for (int o = 16; o; o >>= 1)
            m = fmaxf(m, __shfl_xor_sync(0xffffffffu, m, o));

        float ex = valid ? __expf(ev - m) : 0.f;
        float s = ex;
#pragma unroll
        for (int o = 16; o; o >>= 1)
            s += __shfl_xor_sync(0xffffffffu, s, o);
        float inv = (cnt > 0) ? 1.f / s : 0.f;

        for (int j = 0; j < cnt; j++) {
            float w  = __shfl_sync(0xffffffffu, ex, j) * inv;
            int   sj = __shfl_sync(0xffffffffu, sn, j);
            float2 v = zp[(size_t)sj * (OUT_DIM / 2) + lane];
            ax = fmaf(w, v.x, ax);
            ay = fmaf(w, v.y, ay);
        }
    } else {
        // ---- generic path (deg > 32, rare for mean degree 16) ----
        float m = -INFINITY;
        for (int i = off + lane; i < end; i += 32)
            m = fmaxf(m, __int_as_float(g_pack[i].y));
#pragma unroll
        for (int o = 16; o; o >>= 1)
            m = fmaxf(m, __shfl_xor_sync(0xffffffffu, m, o));

        float s = 0.f;
        for (int i = off + lane; i < end; i += 32)
            s += __expf(__int_as_float(g_pack[i].y) - m);
#pragma unroll
        for (int o = 16; o; o >>= 1)
            s += __shfl_xor_sync(0xffffffffu, s, o);
        float inv = 1.f / s;

        for (int base = off; base < end; base += 32) {
            int n = min(32, end - base);
            bool valid = lane < n;
            int2 p = valid ? g_pack[base + lane] : make_int2(0, 0xff800000);
            float ex = valid ? __expf(__int_as_float(p.y) - m) : 0.f;
            int  sn  = p.x;
            for (int j = 0; j < n; j++) {
                float w  = __shfl_sync(0xffffffffu, ex, j) * inv;
                int   sj = __shfl_sync(0xffffffffu, sn, j);
                float2 v = zp[(size_t)sj * (OUT_DIM / 2) + lane];
                ax = fmaf(w, v.x, ax);
                ay = fmaf(w, v.y, ay);
            }
        }
    }

    // ELU + store (covers every out element -> no separate init)
    float2 r;
    r.x = ax > 0.f ? ax : (__expf(ax) - 1.f);
    r.y = ay > 0.f ? ay : (__expf(ay) - 1.f);
    ((float2*)out)[(size_t)warp * (OUT_DIM / 2) + lane] = r;
}

// ---------------------------------------------------------------------------
extern "C" void kernel_launch(void* const* d_in, const int* in_sizes, int n_in,
                              void* d_out, int out_size) {
    const float* h   = (const float*)d_in[0];
    const float* W   = (const float*)d_in[1];
    const int*   src = (const int*)d_in[2];
    const int*   dst = (const int*)d_in[3];
    float* out = (float*)d_out;

    int n_nodes = in_sizes[0] / IN_DIM;
    int n_edges = in_sizes[2];
    int nblocks = (n_nodes + SCAN_BLK - 1) / SCAN_BLK;

    // K0: zero degree counters
    init_kernel<<<nblocks, SCAN_BLK>>>(n_nodes);
    // K1: z = h @ W^T
    gemm_kernel<<<(n_nodes + 127) / 128, 256>>>(h, W, n_nodes);
    // K2: edge scores + in-degree counts
    {
        long long threads = (long long)n_edges * 16;
        edge_score_kernel<<<(unsigned)((threads + 255) / 256), 256>>>(src, dst, n_edges);
    }
    // K3: exclusive scan deg -> off
    scan_part_kernel<<<nblocks, SCAN_BLK>>>(n_nodes);
    scan_top_kernel<<<1, MAX_BLKS>>>(nblocks);
    scan_add_kernel<<<nblocks, SCAN_BLK>>>(n_nodes, n_edges);
    // K4: scatter packed {src, e} into CSR
    scatter_kernel<<<(n_edges + 255) / 256, 256>>>(src, dst, n_edges);
    // K5: fused softmax + aggregation + ELU
    agg_kernel<<<(n_nodes * 32 + 255) / 256, 256>>>(out, n_nodes);
}